// round 1
// baseline (speedup 1.0000x reference)
#include <cuda_runtime.h>
#include <cstdint>

// Axial attention over width, fused per-(b,h) CTA.
// B=16, C=512, C8=64, H=W=64, MAX_LEN=512.
//
// SMEM layout (fp32 words):
//   Xs  [512][64]   x tile for this (b,h)                 131072 B
//   Ws  [128][64]   weight chunk (Wq+Wk, or Wv d-chunk)    32768 B
//   Qs  [64][64] / Ks [64][64]  (later aliased as Vs[128][64])  32768 B
//   S   [64][68]    attention scores (padded pitch)        17408 B
//   Pt  [64][68]    softmax output, TRANSPOSED [v][w]      17408 B
//   total                                                 231424 B

#define NT 512

extern "C" __global__ void __launch_bounds__(NT, 1)
axial_attn_kernel(const float* __restrict__ x,
                  const float* __restrict__ Wq, const float* __restrict__ bq,
                  const float* __restrict__ Wk, const float* __restrict__ bk,
                  const float* __restrict__ Wv, const float* __restrict__ bv,
                  const float* __restrict__ relh, const float* __restrict__ relw,
                  float* __restrict__ out)
{
    extern __shared__ float smem[];
    float* Xs = smem;                 // [512][64]
    float* Ws = Xs + 512 * 64;        // [128][64]
    float* Qs = Ws + 128 * 64;        // [64][64]
    float* Ks = Qs + 64 * 64;         // [64][64]
    float* Vs = Qs;                   // [128][64] alias (after scores done)
    float* S  = Ks + 64 * 64;         // [64][68]
    float* Pt = S + 64 * 68;          // [64][68]

    const int h = blockIdx.x;
    const int b = blockIdx.y;
    const int t = threadIdx.x;

    const int tv = t & 15;            // pixel (w / v) group
    const int td = t >> 4;            // output-channel group (0..31)
    const int w0 = tv * 4;
    const int o0 = td * 4;

    // ------------------------------------------------------------------
    // Phase 0: load X[b, :, h, :]  ->  Xs[c][w]   (512 rows of 64 floats)
    // ------------------------------------------------------------------
    const float* xbase = x + ((size_t)b * 512 * 4096) + (size_t)h * 64;
    #pragma unroll
    for (int i = t; i < 512 * 16; i += NT) {
        int c  = i >> 4;
        int c4 = i & 15;
        float4 v4 = *(const float4*)(xbase + (size_t)c * 4096 + c4 * 4);
        *(float4*)&Xs[c * 64 + c4 * 4] = v4;
    }
    __syncthreads();

    // ------------------------------------------------------------------
    // Phase 1: Q,K projection. 128 outputs (64 Q + 64 K) x 64 pixels.
    // K-dim 512 processed in 8 chunks of 64 staged through Ws.
    // ------------------------------------------------------------------
    float acc[4][4];
    #pragma unroll
    for (int i = 0; i < 4; i++)
        #pragma unroll
        for (int j = 0; j < 4; j++) acc[i][j] = 0.f;

    for (int cc = 0; cc < 8; cc++) {
        // stage Wq/Wk chunk: Ws[o][c], o<64 -> Wq, o>=64 -> Wk
        #pragma unroll
        for (int i = t; i < 2048; i += NT) {
            int o  = i >> 4;
            int c4 = i & 15;
            const float* src = (o < 64)
                ? (Wq + (size_t)o * 512 + cc * 64 + c4 * 4)
                : (Wk + (size_t)(o - 64) * 512 + cc * 64 + c4 * 4);
            *(float4*)&Ws[o * 64 + c4 * 4] = *(const float4*)src;
        }
        __syncthreads();

        #pragma unroll 4
        for (int c = 0; c < 64; c++) {
            float4 xv = *(const float4*)&Xs[(cc * 64 + c) * 64 + w0];
            #pragma unroll
            for (int i = 0; i < 4; i++) {
                float wv = Ws[(o0 + i) * 64 + c];
                acc[i][0] += wv * xv.x;
                acc[i][1] += wv * xv.y;
                acc[i][2] += wv * xv.z;
                acc[i][3] += wv * xv.w;
            }
        }
        __syncthreads();
    }

    // epilogue: bias + relative position, write Qs[o][w], Ks[o][w]
    #pragma unroll
    for (int i = 0; i < 4; i++) {
        int o = o0 + i;
        if (o < 64) {
            float add = bq[o] + relh[o * 512 + h];   // same for all w
            float4 r = make_float4(acc[i][0] + add, acc[i][1] + add,
                                   acc[i][2] + add, acc[i][3] + add);
            *(float4*)&Qs[o * 64 + w0] = r;
        } else {
            int ok = o - 64;
            float bb = bk[ok];
            float4 r = make_float4(acc[i][0] + bb + relw[ok * 512 + (w0 + 0)],
                                   acc[i][1] + bb + relw[ok * 512 + (w0 + 1)],
                                   acc[i][2] + bb + relw[ok * 512 + (w0 + 2)],
                                   acc[i][3] + bb + relw[ok * 512 + (w0 + 3)]);
            *(float4*)&Ks[ok * 64 + w0] = r;
        }
    }
    __syncthreads();

    // ------------------------------------------------------------------
    // Phase 2: scores S[w][v] = sum_c Qs[c][w] * Ks[c][v]
    // 4096 outputs, 8 per thread (2w x 4v)
    // ------------------------------------------------------------------
    {
        int sv = (t & 15) * 4;
        int sw = (t >> 4) * 2;
        float s00 = 0.f, s01 = 0.f, s02 = 0.f, s03 = 0.f;
        float s10 = 0.f, s11 = 0.f, s12 = 0.f, s13 = 0.f;
        #pragma unroll 4
        for (int c = 0; c < 64; c++) {
            float4 kv = *(const float4*)&Ks[c * 64 + sv];
            float q0 = Qs[c * 64 + sw];
            float q1 = Qs[c * 64 + sw + 1];
            s00 += q0 * kv.x; s01 += q0 * kv.y; s02 += q0 * kv.z; s03 += q0 * kv.w;
            s10 += q1 * kv.x; s11 += q1 * kv.y; s12 += q1 * kv.z; s13 += q1 * kv.w;
        }
        *(float4*)&S[sw * 68 + sv]       = make_float4(s00, s01, s02, s03);
        *(float4*)&S[(sw + 1) * 68 + sv] = make_float4(s10, s11, s12, s13);
    }
    __syncthreads();

    // ------------------------------------------------------------------
    // Phase 3: softmax over v (row-wise), write TRANSPOSED Pt[v][w]
    // ------------------------------------------------------------------
    {
        int warp = t >> 5;
        int lane = t & 31;
        for (int r = warp; r < 64; r += 16) {
            float a0 = S[r * 68 + lane];
            float a1 = S[r * 68 + lane + 32];
            float m = fmaxf(a0, a1);
            #pragma unroll
            for (int off = 16; off > 0; off >>= 1)
                m = fmaxf(m, __shfl_xor_sync(0xffffffffu, m, off));
            float e0 = __expf(a0 - m);
            float e1 = __expf(a1 - m);
            float s = e0 + e1;
            #pragma unroll
            for (int off = 16; off > 0; off >>= 1)
                s += __shfl_xor_sync(0xffffffffu, s, off);
            float inv = 1.f / s;
            Pt[lane * 68 + r]        = e0 * inv;
            Pt[(lane + 32) * 68 + r] = e1 * inv;
        }
    }
    __syncthreads();

    // ------------------------------------------------------------------
    // Phase 4: V projection (d-chunks of 128) fused with AV.
    //   V[d][v] = sum_c Wv[d][c] Xs[c][v] + bv[d]     -> Vs (alias of Qs/Ks)
    //   out[d][w] = sum_v Pt[v][w] * Vs[d][v]
    // ------------------------------------------------------------------
    for (int dc = 0; dc < 4; dc++) {
        const int D = dc * 128;

        float vacc[4][4];
        #pragma unroll
        for (int i = 0; i < 4; i++)
            #pragma unroll
            for (int j = 0; j < 4; j++) vacc[i][j] = 0.f;

        for (int cc = 0; cc < 8; cc++) {
            #pragma unroll
            for (int i = t; i < 2048; i += NT) {
                int dd = i >> 4;
                int c4 = i & 15;
                *(float4*)&Ws[dd * 64 + c4 * 4] =
                    *(const float4*)(Wv + (size_t)(D + dd) * 512 + cc * 64 + c4 * 4);
            }
            __syncthreads();

            #pragma unroll 4
            for (int c = 0; c < 64; c++) {
                float4 xv = *(const float4*)&Xs[(cc * 64 + c) * 64 + w0];
                #pragma unroll
                for (int i = 0; i < 4; i++) {
                    float wv = Ws[(o0 + i) * 64 + c];
                    vacc[i][0] += wv * xv.x;
                    vacc[i][1] += wv * xv.y;
                    vacc[i][2] += wv * xv.z;
                    vacc[i][3] += wv * xv.w;
                }
            }
            __syncthreads();
        }

        // bias + store V chunk to Vs[dd][v]
        #pragma unroll
        for (int i = 0; i < 4; i++) {
            float bb = bv[D + o0 + i];
            float4 r = make_float4(vacc[i][0] + bb, vacc[i][1] + bb,
                                   vacc[i][2] + bb, vacc[i][3] + bb);
            *(float4*)&Vs[(o0 + i) * 64 + w0] = r;
        }
        __syncthreads();

        // AV: out[d][w] = sum_v Pt[v][w] * Vs[d][v]
        float oacc[4][4];
        #pragma unroll
        for (int i = 0; i < 4; i++)
            #pragma unroll
            for (int j = 0; j < 4; j++) oacc[i][j] = 0.f;

        #pragma unroll 4
        for (int v = 0; v < 64; v++) {
            float4 p = *(const float4*)&Pt[v * 68 + w0];
            #pragma unroll
            for (int i = 0; i < 4; i++) {
                float vv = Vs[(o0 + i) * 64 + v];
                oacc[i][0] += vv * p.x;
                oacc[i][1] += vv * p.y;
                oacc[i][2] += vv * p.z;
                oacc[i][3] += vv * p.w;
            }
        }

        // write out[b, D+d, h, w0..w0+3]
        #pragma unroll
        for (int i = 0; i < 4; i++) {
            size_t off = (((size_t)b * 512 + (D + o0 + i)) * 64 + h) * 64 + w0;
            *(float4*)&out[off] = make_float4(oacc[i][0], oacc[i][1],
                                              oacc[i][2], oacc[i][3]);
        }
        __syncthreads();   // Vs / Ws reused next d-chunk
    }
}

extern "C" void kernel_launch(void* const* d_in, const int* in_sizes, int n_in,
                              void* d_out, int out_size)
{
    const float* x    = (const float*)d_in[0];
    const float* Wq   = (const float*)d_in[1];
    const float* bq   = (const float*)d_in[2];
    const float* Wk   = (const float*)d_in[3];
    const float* bk   = (const float*)d_in[4];
    const float* Wv   = (const float*)d_in[5];
    const float* bv   = (const float*)d_in[6];
    const float* relh = (const float*)d_in[7];
    const float* relw = (const float*)d_in[8];
    float* out = (float*)d_out;

    const int smem_bytes = (512 * 64 + 128 * 64 + 64 * 64 * 2 + 64 * 68 * 2) * 4; // 231424
    cudaFuncSetAttribute(axial_attn_kernel,
                         cudaFuncAttributeMaxDynamicSharedMemorySize, smem_bytes);

    dim3 grid(64, 16);   // (h, b)
    axial_attn_kernel<<<grid, NT, smem_bytes>>>(x, Wq, bq, Wk, bk, Wv, bv,
                                                relh, relw, out);
}